// round 1
// baseline (speedup 1.0000x reference)
#include <cuda_runtime.h>
#include <math.h>

// Problem constants
#define BB 16
#define NN 4096
#define DD 64
#define OO 12
#define SS 32
#define MM 12
#define AA 32

#define TILE_N 128
#define THREADS 256

#define HT_STRIDE 130   // transposed H tile stride (even for LDS.64, +2 mod 32 banks)
#define WQ_STRIDE 34
#define KEY_STRIDE 34
#define AT_STRIDE 130

// smem float layout
#define SM_HT    0
#define SM_WQT   (SM_HT + 64*HT_STRIDE)          // 8320
#define SM_KEY   (SM_WQT + 64*WQ_STRIDE)         // +2176 = 10496
#define SM_VALG  (SM_KEY + MM*KEY_STRIDE)        // +408  = 10904
#define SM_AT    (SM_VALG + MM*DD)               // +768  = 11672
#define SM_GATE  (SM_AT + MM*AT_STRIDE)          // +1560 = 13232
#define SM_QS    (SM_GATE + 16)                  // 13248
#define SM_CMB   (SM_QS + 32)                    // 13280
#define SM_FLOATS (SM_CMB + 16)                  // 13296
#define SMEM_BYTES (SM_FLOATS * 4)               // 53184 B

#define HT_OUT_OFF   0
#define ATTN_OUT_OFF ((size_t)BB*OO*NN*DD)               // 50331648
#define GATE_OUT_OFF (ATTN_OUT_OFF + (size_t)BB*OO*NN*MM) // 59768832

#define SCALE 0.17677669529663687f   // 1/sqrt(32)
#define TWO_PI 6.283185307179586f

// Packed dual-FMA (fp32x2). ptxas never auto-fuses this; explicit PTX needed (SASS_QUICKREF).
__device__ __forceinline__ float2 ffma2(float2 a, float2 b, float2 c) {
    float2 d;
    asm("{\n"
        ".reg .b64 ra, rb, rc, rd;\n"
        "mov.b64 ra, {%2, %3};\n"
        "mov.b64 rb, {%4, %5};\n"
        "mov.b64 rc, {%6, %7};\n"
        "fma.rn.f32x2 rd, ra, rb, rc;\n"
        "mov.b64 {%0, %1}, rd;\n"
        "}"
        : "=f"(d.x), "=f"(d.y)
        : "f"(a.x), "f"(a.y), "f"(b.x), "f"(b.y), "f"(c.x), "f"(c.y));
    return d;
}

__global__ __launch_bounds__(THREADS, 2)
void stta_kernel(const float* __restrict__ H, const float* __restrict__ ts_out,
                 const float* __restrict__ step_emb, const float* __restrict__ key_emb,
                 const float* __restrict__ val_emb, const float* __restrict__ Wk,
                 const float* __restrict__ Wg, const float* __restrict__ bg,
                 const float* __restrict__ Wq, const float* __restrict__ bq,
                 float* __restrict__ out)
{
    extern __shared__ float s[];
    float* Ht     = s + SM_HT;     // [64][130]  Ht[d][r]
    float* Wqt    = s + SM_WQT;    // [64][34]   Wqt[d][a]
    float* key_s  = s + SM_KEY;    // [12][34]
    float* valg   = s + SM_VALG;   // [12][64]
    float* at     = s + SM_AT;     // [12][130]  attn transposed [m][r]
    float* gate_s = s + SM_GATE;   // [12]
    float* qs_s   = s + SM_QS;     // [32]
    float* cmb_s  = s + SM_CMB;    // [12]

    const int t  = threadIdx.x;
    const int b  = blockIdx.y;
    const int n0 = blockIdx.x * TILE_N;

    // ---- stage H tile transposed (global coalesced; smem stores ~2-way) ----
    const float* Hrow = H + ((size_t)b * NN + n0) * DD;
    #pragma unroll
    for (int i = t; i < TILE_N * DD; i += THREADS) {
        int r = i >> 6, d = i & 63;
        Ht[d * HT_STRIDE + r] = Hrow[i];
    }
    // ---- stage Wq H-part transposed: Wqt[d][a] = Wq[a][d] ----
    for (int i = t; i < AA * DD; i += THREADS) {
        int a = i >> 6, d = i & 63;
        Wqt[d * WQ_STRIDE + a] = __ldg(&Wq[a * (DD + SS) + d]);
    }
    __syncthreads();

    // ---- qh[r][a0..a0+16) in registers: r = t>>1, half h = t&1 ----
    const int r  = t >> 1;
    const int h  = t & 1;
    const int a0 = h * 16;
    float2 qh2[8];
    #pragma unroll
    for (int j = 0; j < 8; j++) qh2[j] = make_float2(0.f, 0.f);
    #pragma unroll 4
    for (int d = 0; d < DD; d++) {
        float hv = Ht[d * HT_STRIDE + r];
        float2 hd = make_float2(hv, hv);
        const float* wrow = &Wqt[d * WQ_STRIDE + a0];
        #pragma unroll
        for (int j = 0; j < 8; j++) {
            float2 w = *(const float2*)(wrow + 2 * j);
            qh2[j] = ffma2(hd, w, qh2[j]);
        }
    }

    const int dd = t & 63;   // delta-phase column
    const int g  = t >> 6;   // delta-phase row group (4 groups x 32 rows)

    #pragma unroll 1
    for (int o = 0; o < OO; o++) {
        __syncthreads();  // protect key_s/valg/at reuse from previous iteration

        const float tod = __ldg(&ts_out[(b * OO + o) * 2 + 0]);
        const float dow = __ldg(&ts_out[(b * OO + o) * 2 + 1]);

        // ---- key, gate ----
        for (int i = t; i < MM * AA; i += THREADS) {
            int m = i >> 5, a = i & 31;
            float ph = (m < 8) ? tod : dow;
            float kf = (m < 8) ? (float)(m + 1) : (float)(m - 7);
            float ang = TWO_PI * ph * kf;
            float sn, cs; sincosf(ang, &sn, &cs);
            key_s[m * KEY_STRIDE + a] =
                sn * __ldg(&Wk[a * 2 + 0]) + cs * __ldg(&Wk[a * 2 + 1]) +
                __ldg(&key_emb[m * AA + a]);
            if (a == 0)
                gate_s[m] = tanhf(sn * __ldg(&Wg[0]) + cs * __ldg(&Wg[1]) + __ldg(&bg[0]));
        }
        // ---- qs[a] = step_emb[b,o,:] . Wq[a, D:] + bq[a] ----
        if (t < AA) {
            float acc = __ldg(&bq[t]);
            const float* se = &step_emb[(b * OO + o) * SS];
            const float* wr = &Wq[t * (DD + SS) + DD];
            #pragma unroll 8
            for (int si = 0; si < SS; si++) acc += __ldg(&se[si]) * __ldg(&wr[si]);
            qs_s[t] = acc;
        }
        __syncthreads();

        // ---- valg = gate * val_emb ; cmb[m] = qs . key[m] ----
        for (int i = t; i < MM * DD; i += THREADS) {
            int m = i >> 6;
            valg[i] = gate_s[m] * __ldg(&val_emb[i]);
        }
        if (t < MM) {
            float acc = 0.f;
            #pragma unroll
            for (int a = 0; a < AA; a++) acc += qs_s[a] * key_s[t * KEY_STRIDE + a];
            cmb_s[t] = acc;
        }
        __syncthreads();

        // ---- logits + softmax (pair of threads per row, packed over a) ----
        float lg[MM];
        #pragma unroll
        for (int m = 0; m < MM; m++) {
            float2 acc = make_float2(0.f, 0.f);
            const float* kr = &key_s[m * KEY_STRIDE + a0];
            #pragma unroll
            for (int j = 0; j < 8; j++) {
                float2 k2 = *(const float2*)(kr + 2 * j);
                acc = ffma2(qh2[j], k2, acc);
            }
            float p = acc.x + acc.y;
            p += __shfl_xor_sync(0xffffffffu, p, 1);  // combine a-halves (t ^ 1 = same r)
            lg[m] = (p + cmb_s[m]) * SCALE;
        }
        float mx = lg[0];
        #pragma unroll
        for (int m = 1; m < MM; m++) mx = fmaxf(mx, lg[m]);
        float sum = 0.f;
        #pragma unroll
        for (int m = 0; m < MM; m++) { lg[m] = __expf(lg[m] - mx); sum += lg[m]; }
        float inv = 1.f / sum;
        #pragma unroll
        for (int j = 0; j < 6; j++) {
            int m = h * 6 + j;
            at[m * AT_STRIDE + r] = lg[m] * inv;
        }
        __syncthreads();

        // ---- attn global write (coalesced via shared) ----
        {
            float* ao = out + ATTN_OUT_OFF + ((size_t)(b * OO + o) * NN + n0) * MM;
            #pragma unroll
            for (int i = t; i < TILE_N * MM; i += THREADS) {
                int rr = i / MM, mm = i - rr * MM;
                ao[i] = at[mm * AT_STRIDE + rr];
            }
        }
        // ---- delta + H_time: thread owns column dd, 32 rows, 2 rows packed ----
        {
            float2 vg[MM];
            #pragma unroll
            for (int m = 0; m < MM; m++) {
                float v = valg[m * DD + dd];
                vg[m] = make_float2(v, v);
            }
            float* ho = out + ((size_t)(b * OO + o) * NN + n0) * DD + dd;
            #pragma unroll 4
            for (int rp = 0; rp < 16; rp++) {
                int rr = g * 32 + rp * 2;
                float2 acc = make_float2(0.f, 0.f);
                #pragma unroll
                for (int m = 0; m < MM; m++) {
                    float2 ap = *(const float2*)&at[m * AT_STRIDE + rr];  // broadcast
                    acc = ffma2(ap, vg[m], acc);
                }
                float2 hv = *(const float2*)&Ht[dd * HT_STRIDE + rr];
                ho[(size_t)rr * DD]       = fmaf(0.1f, acc.x, hv.x);
                ho[(size_t)(rr + 1) * DD] = fmaf(0.1f, acc.y, hv.y);
            }
        }
    }
}

__global__ void gate_out_kernel(const float* __restrict__ ts_out,
                                const float* __restrict__ Wg,
                                const float* __restrict__ bg,
                                float* __restrict__ outg)
{
    int i = blockIdx.x * blockDim.x + threadIdx.x;
    if (i >= BB * OO * MM) return;
    int m = i % MM;
    int bo = i / MM;
    float ph = (m < 8) ? ts_out[bo * 2 + 0] : ts_out[bo * 2 + 1];
    float kf = (m < 8) ? (float)(m + 1) : (float)(m - 7);
    float ang = TWO_PI * ph * kf;
    float sn, cs; sincosf(ang, &sn, &cs);
    outg[i] = tanhf(sn * Wg[0] + cs * Wg[1] + bg[0]);
}

extern "C" void kernel_launch(void* const* d_in, const int* in_sizes, int n_in,
                              void* d_out, int out_size)
{
    const float* H        = (const float*)d_in[0];
    const float* ts_out   = (const float*)d_in[1];
    const float* step_emb = (const float*)d_in[2];
    const float* key_emb  = (const float*)d_in[3];
    const float* val_emb  = (const float*)d_in[4];
    const float* Wk       = (const float*)d_in[5];
    const float* Wg       = (const float*)d_in[6];
    const float* bg       = (const float*)d_in[7];
    const float* Wq       = (const float*)d_in[8];
    const float* bq       = (const float*)d_in[9];
    float* out = (float*)d_out;

    cudaFuncSetAttribute(stta_kernel, cudaFuncAttributeMaxDynamicSharedMemorySize, SMEM_BYTES);

    dim3 grid(NN / TILE_N, BB);
    stta_kernel<<<grid, THREADS, SMEM_BYTES>>>(H, ts_out, step_emb, key_emb, val_emb,
                                               Wk, Wg, bg, Wq, bq, out);
    gate_out_kernel<<<(BB * OO * MM + 255) / 256, 256>>>(ts_out, Wg, bg, out + GATE_OUT_OFF);
}